// round 1
// baseline (speedup 1.0000x reference)
#include <cuda_runtime.h>

#define B_ 32
#define T_ 2048
#define F_ 128
#define U_ 128
#define G_ 384   /* 3U */
#define C_ 11
#define R_ (B_*T_)  /* 65536 rows */

// ---------------------------------------------------------------------------
// Scratch (device globals: no runtime allocation allowed)
// ---------------------------------------------------------------------------
__device__ float g_xg[2][R_ * G_];      // input projections per direction: [dir][b*T+t][384]
__device__ float g_hs[R_ * 2 * U_];     // concat hidden states: [b*T+t][256] (fwd | bwd)

// ---------------------------------------------------------------------------
// Packed fp32x2 helpers (Blackwell fma.rn.f32x2 — 2 fp32 FMAs per instruction)
// ---------------------------------------------------------------------------
__device__ __forceinline__ unsigned long long ffma2(unsigned long long a,
                                                    unsigned long long b,
                                                    unsigned long long c) {
    unsigned long long d;
    asm("fma.rn.f32x2 %0, %1, %2, %3;" : "=l"(d) : "l"(a), "l"(b), "l"(c));
    return d;
}
__device__ __forceinline__ unsigned long long pack2(float x, float y) {
    unsigned long long r;
    asm("mov.b64 %0, {%1, %2};" : "=l"(r) : "f"(x), "f"(y));
    return r;
}
__device__ __forceinline__ float sum2(unsigned long long v) {
    float lo, hi;
    asm("mov.b64 {%0, %1}, %2;" : "=f"(lo), "=f"(hi) : "l"(v));
    return lo + hi;
}

// ---------------------------------------------------------------------------
// Phase 1: xg[dir] = x @ W[dir] + b[dir][0]
// C[65536,384] = A[65536,128] * W[128,384]. Tiled fp32 GEMM.
// TM=64, TN=64, TK=32; 256 threads; 4x4 micro-tile per thread.
// ---------------------------------------------------------------------------
__global__ __launch_bounds__(256) void proj_kernel(
    const float* __restrict__ x,
    const float* __restrict__ Wf, const float* __restrict__ bf,
    const float* __restrict__ Wb, const float* __restrict__ bb)
{
    const int dir = blockIdx.z;
    const float* __restrict__ W    = dir ? Wb : Wf;
    const float* __restrict__ bias = dir ? bb : bf;   // row 0 of [2,384]
    float* __restrict__ Cout = g_xg[dir];

    const int r0 = blockIdx.x * 64;
    const int c0 = blockIdx.y * 64;

    __shared__ float As[64 * 36];   // [i][k], row stride 36 (pad, keeps float4 align)
    __shared__ float Bs[32 * 64];   // [k][j]

    const int tid = threadIdx.x;
    const int tx  = tid & 15;       // col group
    const int ty  = tid >> 4;       // row group

    float acc[4][4];
    #pragma unroll
    for (int i = 0; i < 4; i++)
        #pragma unroll
        for (int j = 0; j < 4; j++) acc[i][j] = 0.f;

    for (int k0 = 0; k0 < F_; k0 += 32) {
        // Load A tile (coalesced float4 along k)
        #pragma unroll
        for (int q = 0; q < 2; q++) {
            int idx = tid + 256 * q;
            int i   = idx >> 3;
            int kk4 = (idx & 7) << 2;
            float4 v = *(const float4*)(x + (size_t)(r0 + i) * F_ + k0 + kk4);
            *(float4*)(As + i * 36 + kk4) = v;
        }
        // Load B tile (coalesced float4 along j)
        #pragma unroll
        for (int q = 0; q < 2; q++) {
            int idx = tid + 256 * q;
            int kk  = idx >> 4;
            int j4  = (idx & 15) << 2;
            float4 v = *(const float4*)(W + (size_t)(k0 + kk) * G_ + c0 + j4);
            *(float4*)(Bs + kk * 64 + j4) = v;
        }
        __syncthreads();

        #pragma unroll
        for (int kk = 0; kk < 32; kk++) {
            float a0 = As[(ty * 4 + 0) * 36 + kk];
            float a1 = As[(ty * 4 + 1) * 36 + kk];
            float a2 = As[(ty * 4 + 2) * 36 + kk];
            float a3 = As[(ty * 4 + 3) * 36 + kk];
            float4 b = *(const float4*)(Bs + kk * 64 + tx * 4);
            acc[0][0] += a0 * b.x; acc[0][1] += a0 * b.y; acc[0][2] += a0 * b.z; acc[0][3] += a0 * b.w;
            acc[1][0] += a1 * b.x; acc[1][1] += a1 * b.y; acc[1][2] += a1 * b.z; acc[1][3] += a1 * b.w;
            acc[2][0] += a2 * b.x; acc[2][1] += a2 * b.y; acc[2][2] += a2 * b.z; acc[2][3] += a2 * b.w;
            acc[3][0] += a3 * b.x; acc[3][1] += a3 * b.y; acc[3][2] += a3 * b.z; acc[3][3] += a3 * b.w;
        }
        __syncthreads();
    }

    #pragma unroll
    for (int di = 0; di < 4; di++) {
        int r = r0 + ty * 4 + di;
        int c = c0 + tx * 4;
        float4 v;
        v.x = acc[di][0] + bias[c + 0];
        v.y = acc[di][1] + bias[c + 1];
        v.z = acc[di][2] + bias[c + 2];
        v.w = acc[di][3] + bias[c + 3];
        *(float4*)(Cout + (size_t)r * G_ + c) = v;
    }
}

// ---------------------------------------------------------------------------
// Phase 2: GRU recurrence. One persistent block per (batch, direction).
// 384 threads: thread g owns gate column g. U[:,g] lives in registers as
// 64 packed f32x2 values; h (128 floats) is broadcast from shared memory.
// Gate order (Keras reset_after=True): z, r, h.
//   z  = sigmoid(xz + rz)          (rz includes recurrent bias)
//   r  = sigmoid(xr + rr)
//   hh = relu(xh + r * rh)         (rh includes recurrent bias; r scales rec part only)
//   h' = z*h + (1-z)*hh
// Backward direction processes t = T-1 .. 0 and writes at index t.
// ---------------------------------------------------------------------------
__global__ __launch_bounds__(384, 1) void gru_kernel(
    const float* __restrict__ Uf, const float* __restrict__ bf,
    const float* __restrict__ Ub, const float* __restrict__ bb)
{
    const int b   = blockIdx.x;
    const int dir = blockIdx.y;
    const int g   = threadIdx.x;   // 0..383

    const float* __restrict__ Um = dir ? Ub : Uf;
    const float  myb2 = (dir ? bb : bf)[G_ + g];             // recurrent bias b[1][g]
    const float* __restrict__ xg = g_xg[dir] + (size_t)b * T_ * G_;
    float* __restrict__ hout = g_hs + (size_t)b * T_ * (2 * U_) + (dir ? U_ : 0);

    // Load U column g into registers, packed in k-pairs (coalesced across g).
    unsigned long long ucol[64];
    #pragma unroll
    for (int q = 0; q < 64; q++)
        ucol[q] = pack2(Um[(2 * q) * G_ + g], Um[(2 * q + 1) * G_ + g]);

    __shared__ __align__(16) float h_sh[U_];
    __shared__ float s_sh[G_];
    __shared__ float xh_sh[U_];

    if (g < U_) h_sh[g] = 0.f;
    __syncthreads();

    int t = dir ? (T_ - 1) : 0;
    float xv = xg[(size_t)t * G_ + g];

    for (int s = 0; s < T_; s++) {
        const int tn = dir ? (T_ - 2 - s) : (s + 1);
        // Prefetch next timestep's input projection (hidden under the dot product)
        const float xnext = (s + 1 < T_) ? xg[(size_t)tn * G_ + g] : 0.f;

        // rec[g] = h . U[:,g]  via packed fp32x2 FMAs (4 independent chains)
        unsigned long long acc0 = pack2(0.f, 0.f);
        unsigned long long acc1 = acc0, acc2 = acc0, acc3 = acc0;
        const ulonglong2* hp = (const ulonglong2*)h_sh;
        #pragma unroll
        for (int q = 0; q < 32; q += 2) {
            ulonglong2 h01 = hp[q];
            ulonglong2 h23 = hp[q + 1];
            acc0 = ffma2(h01.x, ucol[2 * q + 0], acc0);
            acc1 = ffma2(h01.y, ucol[2 * q + 1], acc1);
            acc2 = ffma2(h23.x, ucol[2 * q + 2], acc2);
            acc3 = ffma2(h23.y, ucol[2 * q + 3], acc3);
        }
        const float rec = sum2(acc0) + sum2(acc1) + sum2(acc2) + sum2(acc3) + myb2;

        if (g < 2 * U_) {
            s_sh[g] = xv + rec;            // full pre-activation for z, r
        } else {
            s_sh[g] = rec;                 // recurrent part only for h-gate
            xh_sh[g - 2 * U_] = xv;        // input part of h-gate kept separate
        }
        __syncthreads();

        if (g < U_) {
            const float z  = 1.f / (1.f + expf(-s_sh[g]));
            const float r  = 1.f / (1.f + expf(-s_sh[g + U_]));
            const float hh = fmaxf(xh_sh[g] + r * s_sh[g + 2 * U_], 0.f);
            const float hn = z * h_sh[g] + (1.f - z) * hh;
            h_sh[g] = hn;
            hout[(size_t)t * (2 * U_) + g] = hn;
        }
        __syncthreads();

        xv = xnext;
        t  = tn;
    }
}

// ---------------------------------------------------------------------------
// Phase 3: logits = h_cat @ Wd + bd ; softmax over C. One warp per (b,t) row.
// ---------------------------------------------------------------------------
__global__ __launch_bounds__(128) void dense_kernel(
    const float* __restrict__ Wd, const float* __restrict__ bd,
    float* __restrict__ out)
{
    __shared__ float wds[2 * U_ * C_];   // 2816 floats
    __shared__ float bds[C_];
    const int tid = threadIdx.x;
    for (int i = tid; i < 2 * U_ * C_; i += 128) wds[i] = Wd[i];
    if (tid < C_) bds[tid] = bd[tid];
    __syncthreads();

    const int w = tid >> 5;
    const int l = tid & 31;
    const size_t row = (size_t)blockIdx.x * 4 + w;

    const float* __restrict__ h = g_hs + row * (2 * U_);
    float hv[8];
    #pragma unroll
    for (int q = 0; q < 8; q++) hv[q] = h[l + 32 * q];

    float logit[C_];
    #pragma unroll
    for (int c = 0; c < C_; c++) {
        float a = 0.f;
        #pragma unroll
        for (int q = 0; q < 8; q++) a += hv[q] * wds[(l + 32 * q) * C_ + c];
        logit[c] = a;
    }
    #pragma unroll
    for (int c = 0; c < C_; c++) {
        #pragma unroll
        for (int off = 16; off; off >>= 1)
            logit[c] += __shfl_xor_sync(0xffffffffu, logit[c], off);
        logit[c] += bds[c];
    }

    float m = logit[0];
    #pragma unroll
    for (int c = 1; c < C_; c++) m = fmaxf(m, logit[c]);
    float e[C_], ssum = 0.f;
    #pragma unroll
    for (int c = 0; c < C_; c++) { e[c] = expf(logit[c] - m); ssum += e[c]; }
    const float inv = 1.f / ssum;
    if (l == 0) {
        #pragma unroll
        for (int c = 0; c < C_; c++) out[row * C_ + c] = e[c] * inv;
    }
}

// ---------------------------------------------------------------------------
// Launch: three dependent kernels on the capture stream. No sync, no alloc.
// Input order (metadata): x, W_f, U_f, b_f, W_b, U_b, b_b, Wd, bd (all f32).
// ---------------------------------------------------------------------------
extern "C" void kernel_launch(void* const* d_in, const int* in_sizes, int n_in,
                              void* d_out, int out_size)
{
    const float* x  = (const float*)d_in[0];
    const float* Wf = (const float*)d_in[1];
    const float* Uf = (const float*)d_in[2];
    const float* bf = (const float*)d_in[3];
    const float* Wb = (const float*)d_in[4];
    const float* Ub = (const float*)d_in[5];
    const float* bb = (const float*)d_in[6];
    const float* Wd = (const float*)d_in[7];
    const float* bd = (const float*)d_in[8];
    float* out = (float*)d_out;

    proj_kernel<<<dim3(R_ / 64, G_ / 64, 2), 256>>>(x, Wf, bf, Wb, bb);
    gru_kernel<<<dim3(B_, 2), 384>>>(Uf, bf, Ub, bb);
    dense_kernel<<<R_ / 4, 128>>>(Wd, bd, out);
}